// round 16
// baseline (speedup 1.0000x reference)
#include <cuda_runtime.h>
#include <math.h>

#define N_NODES 100000
#define N_EDGES 1600000
#define HALF_E  (N_EDGES / 2)
#define WJPITCH 29

__device__ float g_dot[N_EDGES];
__device__ float g_m[N_NODES];
__device__ float g_s[N_NODES];
__device__ float g_q[N_NODES * 8];   // per-node q: [q0_o0,q0_o1, q1_o0m0..m2, q1_o1m0..m2]

// shared weights, mean-centered where LN-folding applies
struct SWS {
    float W1[4][3][16];    // column-mean-subtracted
    float b1[4][16];       // mean-subtracted
    float g1v[4][16], be1v[4][16];
    float W2[4][16][16];   // column-mean-subtracted (over j)
    float b2[4][16];       // mean-subtracted
    float g2v[4][16], be2v[4][16];
    float W3a[3][16][4];   // W3_00, W3_01, W3_10  ([k][o])
    float b3a[3][4];
    float W3b[16][12];     // W3_11
    float b3b[12];
};

// LN without mean pass (input is mean-free by weight construction) + ReLU.
// var = sum(h^2)/16 >= 0 always -> NaN-proof.
__device__ __forceinline__ void ln_lite(float* h, const float* g, const float* be) {
    float q0 = h[0] * h[0];   q0 = fmaf(h[1], h[1], q0);
    float q1 = h[2] * h[2];   q1 = fmaf(h[3], h[3], q1);
    float q2 = h[4] * h[4];   q2 = fmaf(h[5], h[5], q2);
    float q3 = h[6] * h[6];   q3 = fmaf(h[7], h[7], q3);
    float q4 = h[8] * h[8];   q4 = fmaf(h[9], h[9], q4);
    float q5 = h[10] * h[10]; q5 = fmaf(h[11], h[11], q5);
    float q6 = h[12] * h[12]; q6 = fmaf(h[13], h[13], q6);
    float q7 = h[14] * h[14]; q7 = fmaf(h[15], h[15], q7);
    q0 += q1; q2 += q3; q4 += q5; q6 += q7;
    q0 += q2; q4 += q6;
    float ss = q0 + q4;
    float inv = rsqrtf(fmaf(ss, 0.0625f, 1e-5f));
#pragma unroll
    for (int j = 0; j < 16; j++)
        h[j] = fmaxf(fmaf(h[j] * inv, g[j], be[j]), 0.f);
}

// scalar radial MLP trunk: 3 -> 16 -> LN -> 16 -> LN, result in out[16]
__device__ __forceinline__ void radial_s(
    const float (*W1)[16], const float* b1, const float* g1, const float* be1,
    const float (*W2)[16], const float* b2, const float* g2, const float* be2,
    float v0, float v1, float v2, float* out)
{
    float h[16];
#pragma unroll
    for (int j = 0; j < 16; j++)
        h[j] = fmaf(v0, W1[0][j], fmaf(v1, W1[1][j], fmaf(v2, W1[2][j], b1[j])));
    ln_lite(h, g1, be1);
#pragma unroll
    for (int j = 0; j < 16; j++) out[j] = b2[j];
#pragma unroll
    for (int k = 0; k < 16; k++) {
#pragma unroll
        for (int j = 0; j < 16; j++)
            out[j] = fmaf(h[k], W2[k][j], out[j]);
    }
    ln_lite(out, g2, be2);
}

__device__ __forceinline__ void atomicMaxF(float* addr, float val) {
    if (val >= 0.f) atomicMax((int*)addr, __float_as_int(val));
    else            atomicMin((unsigned int*)addr, __float_as_uint(val));
}

// init m/s AND precompute per-node q
__global__ void init_kernel(const float* __restrict__ f0, const float* __restrict__ f1,
                            const float* __restrict__ wq) {
    int n = blockIdx.x * blockDim.x + threadIdx.x;
    if (n >= N_NODES) return;
    g_m[n] = -INFINITY;
    g_s[n] = 0.f;
    float2 f = ((const float2*)f0)[n];
    float f1v[6];
    {
        const float2* p = (const float2*)f1 + 3 * n;
        float2 x;
        x = p[0]; f1v[0] = x.x; f1v[1] = x.y;
        x = p[1]; f1v[2] = x.x; f1v[3] = x.y;
        x = p[2]; f1v[4] = x.x; f1v[5] = x.y;
    }
    float q[8];
#pragma unroll
    for (int o = 0; o < 2; o++) {
        q[o] = fmaf(wq[o * 2 + 0], f.x, wq[o * 2 + 1] * f.y);
#pragma unroll
        for (int m = 0; m < 3; m++)
            q[2 + o * 3 + m] = fmaf(wq[4 + o * 2 + 0], f1v[m], wq[4 + o * 2 + 1] * f1v[3 + m]);
    }
    float4* dst = (float4*)&g_q[n * 8];
    dst[0] = make_float4(q[0], q[1], q[2], q[3]);
    dst[1] = make_float4(q[4], q[5], q[6], q[7]);
}

__global__ __launch_bounds__(128, 4) void edge_kernel(
    const float* __restrict__ f0, const float* __restrict__ f1,
    const float* __restrict__ dist,
    const int* __restrict__ u, const int* __restrict__ v,
    const float* __restrict__ wj00, const float* __restrict__ wj01,
    const float* __restrict__ wj10, const float* __restrict__ wj11,
    const float* __restrict__ rW1, const float* __restrict__ rb1,
    const float* __restrict__ g1, const float* __restrict__ be1,
    const float* __restrict__ rW2, const float* __restrict__ rb2,
    const float* __restrict__ g2, const float* __restrict__ be2,
    const float* __restrict__ W3_00, const float* __restrict__ b3_00,
    const float* __restrict__ W3_01, const float* __restrict__ b3_01,
    const float* __restrict__ W3_10, const float* __restrict__ b3_10,
    const float* __restrict__ W3_11, const float* __restrict__ b3_11)
{
    __shared__ SWS sw;
    __shared__ float wj11s[128 * WJPITCH];
    __shared__ float mW1[12], mb1[4], mW2[64], mb2[4];
    {
        int t = threadIdx.x;
        // ---- raw copy ----
        for (int i = t; i < 192;  i += 128) ((float*)sw.W1)[i]   = rW1[i];
        for (int i = t; i < 64;   i += 128) {
            ((float*)sw.b1)[i]   = rb1[i];
            ((float*)sw.g1v)[i]  = g1[i];
            ((float*)sw.be1v)[i] = be1[i];
            ((float*)sw.b2)[i]   = rb2[i];
            ((float*)sw.g2v)[i]  = g2[i];
            ((float*)sw.be2v)[i] = be2[i];
            ((float*)sw.W3a[0])[i] = W3_00[i];
            ((float*)sw.W3a[1])[i] = W3_01[i];
            ((float*)sw.W3a[2])[i] = W3_10[i];
        }
        for (int i = t; i < 1024; i += 128) ((float*)sw.W2)[i]   = rW2[i];
        for (int i = t; i < 192;  i += 128) ((float*)sw.W3b)[i]  = W3_11[i];
        for (int i = t; i < 4;    i += 128) {
            sw.b3a[0][i] = b3_00[i];
            sw.b3a[1][i] = b3_01[i];
            sw.b3a[2][i] = b3_10[i];
        }
        for (int i = t; i < 12;   i += 128) sw.b3b[i] = b3_11[i];
        // wj11 slab staging (coalesced)
        const float* src = wj11 + (long long)blockIdx.x * 128 * 27;
#pragma unroll
        for (int k = 0; k < 27; k++) {
            int i = t + 128 * k;
            int e = i / 27, j = i - e * 27;
            wj11s[e * WJPITCH + j] = src[i];
        }
        __syncthreads();
        // ---- compute column means for LN folding ----
        if (t < 64) {                       // W2 rows: (i,k)
            int i = t >> 4, k = t & 15;
            float s = 0.f;
#pragma unroll
            for (int j = 0; j < 16; j++) s += sw.W2[i][k][j];
            mW2[t] = s * 0.0625f;
        } else if (t < 76) {                // W1 rows: (i,k), 12 rows
            int r = t - 64;
            int i = r / 3, k = r - 3 * i;
            float s = 0.f;
#pragma unroll
            for (int j = 0; j < 16; j++) s += sw.W1[i][k][j];
            mW1[r] = s * 0.0625f;
        } else if (t < 80) {                // b1 means
            int i = t - 76;
            float s = 0.f;
#pragma unroll
            for (int j = 0; j < 16; j++) s += sw.b1[i][j];
            mb1[i] = s * 0.0625f;
        } else if (t < 84) {                // b2 means
            int i = t - 80;
            float s = 0.f;
#pragma unroll
            for (int j = 0; j < 16; j++) s += sw.b2[i][j];
            mb2[i] = s * 0.0625f;
        }
        __syncthreads();
        // ---- subtract means (exact LN mean-folding) ----
        for (int i = t; i < 1024; i += 128) {
            int mi = i >> 4;                 // (i*16+k)
            ((float*)sw.W2)[i] -= mW2[mi];
        }
        for (int i = t; i < 192; i += 128) {
            int mi = i >> 4;                 // (i*3+k)
            ((float*)sw.W1)[i] -= mW1[mi];
        }
        for (int i = t; i < 64; i += 128) {
            int mi = i >> 4;
            ((float*)sw.b1)[i] -= mb1[mi];
            ((float*)sw.b2)[i] -= mb2[mi];
        }
    }
    __syncthreads();

    int e = blockIdx.x * 128 + threadIdx.x;

    // ---- hoisted per-edge loads ----
    int uu = u[e], vv = v[e];
    float v2 = dist[e];
    float wj00e = wj00[e];
    float wj01v[3], wj10v[3];
#pragma unroll
    for (int m = 0; m < 3; m++) { wj01v[m] = wj01[3 * e + m]; wj10v[m] = wj10[3 * e + m]; }
    float2 fu = ((const float2*)f0)[uu];
    float2 fv = ((const float2*)f0)[vv];
    float f1v[6];
    {
        const float2* p0 = (const float2*)f1 + 3 * vv;
        float2 x;
        x = p0[0]; f1v[0] = x.x; f1v[1] = x.y;
        x = p0[1]; f1v[2] = x.x; f1v[3] = x.y;
        x = p0[2]; f1v[4] = x.x; f1v[5] = x.y;
    }
    float4 qa = ((const float4*)&g_q[vv * 8])[0];
    float4 qb = ((const float4*)&g_q[vv * 8])[1];

    float v0 = fu.x * fv.x;
    float v1 = fu.y * fv.y;

    float h2[16];
    float k00, k01;
    float k1[2][3];

    // ---- MLP0 (l=0,k=0) ----
    radial_s(sw.W1[0], sw.b1[0], sw.g1v[0], sw.be1v[0],
             sw.W2[0], sw.b2[0], sw.g2v[0], sw.be2v[0], v0, v1, v2, h2);
    {
        float R[4] = {sw.b3a[0][0], sw.b3a[0][1], sw.b3a[0][2], sw.b3a[0][3]};
#pragma unroll
        for (int k = 0; k < 16; k++) {
#pragma unroll
            for (int o = 0; o < 4; o++) R[o] = fmaf(h2[k], sw.W3a[0][k][o], R[o]);
        }
        k00 = wj00e * fmaf(R[0], fv.x, R[1] * fv.y);
        k01 = wj00e * fmaf(R[2], fv.x, R[3] * fv.y);
    }

    // ---- MLP1 (l=0,k=1) ----
    radial_s(sw.W1[1], sw.b1[1], sw.g1v[1], sw.be1v[1],
             sw.W2[1], sw.b2[1], sw.g2v[1], sw.be2v[1], v0, v1, v2, h2);
    {
        float R[4] = {sw.b3a[1][0], sw.b3a[1][1], sw.b3a[1][2], sw.b3a[1][3]};
#pragma unroll
        for (int k = 0; k < 16; k++) {
#pragma unroll
            for (int o = 0; o < 4; o++) R[o] = fmaf(h2[k], sw.W3a[1][k][o], R[o]);
        }
        float t0 = fmaf(wj01v[0], f1v[0], fmaf(wj01v[1], f1v[1], wj01v[2] * f1v[2]));
        float t1 = fmaf(wj01v[0], f1v[3], fmaf(wj01v[1], f1v[4], wj01v[2] * f1v[5]));
        k00 = fmaf(R[0], t0, fmaf(R[1], t1, k00));
        k01 = fmaf(R[2], t0, fmaf(R[3], t1, k01));
    }

    // ---- MLP2 (l=1,k=0) ----
    radial_s(sw.W1[2], sw.b1[2], sw.g1v[2], sw.be1v[2],
             sw.W2[2], sw.b2[2], sw.g2v[2], sw.be2v[2], v0, v1, v2, h2);
    {
        float R[4] = {sw.b3a[2][0], sw.b3a[2][1], sw.b3a[2][2], sw.b3a[2][3]};
#pragma unroll
        for (int k = 0; k < 16; k++) {
#pragma unroll
            for (int o = 0; o < 4; o++) R[o] = fmaf(h2[k], sw.W3a[2][k][o], R[o]);
        }
        float d0 = fmaf(R[0], fv.x, R[1] * fv.y);
        float d1 = fmaf(R[2], fv.x, R[3] * fv.y);
#pragma unroll
        for (int l = 0; l < 3; l++) {
            k1[0][l] = d0 * wj10v[l];
            k1[1][l] = d1 * wj10v[l];
        }
    }

    // ---- MLP3 (l=1,k=1) ----
    radial_s(sw.W1[3], sw.b1[3], sw.g1v[3], sw.be1v[3],
             sw.W2[3], sw.b2[3], sw.g2v[3], sw.be2v[3], v0, v1, v2, h2);
    {
        float R[12];
#pragma unroll
        for (int o = 0; o < 12; o++) R[o] = sw.b3b[o];
#pragma unroll
        for (int k = 0; k < 16; k++) {
#pragma unroll
            for (int o = 0; o < 12; o++) R[o] = fmaf(h2[k], sw.W3b[k][o], R[o]);
        }
        const float* wr = &wj11s[threadIdx.x * WJPITCH];
#pragma unroll
        for (int j = 0; j < 3; j++) {
#pragma unroll
            for (int l = 0; l < 3; l++) {
                float w0 = wr[9 * j + 3 * l], w1 = wr[9 * j + 3 * l + 1], w2 = wr[9 * j + 3 * l + 2];
                float s0 = fmaf(w0, f1v[0], fmaf(w1, f1v[1], w2 * f1v[2]));
                float s1 = fmaf(w0, f1v[3], fmaf(w1, f1v[4], w2 * f1v[5]));
                k1[0][l] = fmaf(R[4 * j + 0], s0, fmaf(R[4 * j + 1], s1, k1[0][l]));
                k1[1][l] = fmaf(R[4 * j + 2], s0, fmaf(R[4 * j + 3], s1, k1[1][l]));
            }
        }
    }

    // ---- dot with precomputed q ----
    float dot = qa.x * k00;
    dot = fmaf(qa.y, k01, dot);
    dot = fmaf(qa.z, k1[0][0], dot);
    dot = fmaf(qa.w, k1[0][1], dot);
    dot = fmaf(qb.x, k1[0][2], dot);
    dot = fmaf(qb.y, k1[1][0], dot);
    dot = fmaf(qb.z, k1[1][1], dot);
    dot = fmaf(qb.w, k1[1][2], dot);

    g_dot[e] = dot;
    atomicMaxF(&g_m[vv], dot);
}

__global__ void exp_kernel(const int* __restrict__ v, float* __restrict__ out) {
    int t = blockIdx.x * 256 + threadIdx.x;
    if (t >= HALF_E) return;
    int2 vv = ((const int2*)v)[t];
    float2 d = ((const float2*)g_dot)[t];
    float p0 = __expf(d.x - g_m[vv.x]);
    float p1 = __expf(d.y - g_m[vv.y]);
    float2 po; po.x = p0; po.y = p1;
    ((float2*)out)[t] = po;
    atomicAdd(&g_s[vv.x], p0);
    atomicAdd(&g_s[vv.y], p1);
}

__global__ void norm_kernel(const int* __restrict__ v, float* __restrict__ out) {
    int t = blockIdx.x * 256 + threadIdx.x;
    if (t >= HALF_E) return;
    int2 vv = ((const int2*)v)[t];
    float2 o = ((const float2*)out)[t];
    o.x = o.x / g_s[vv.x];
    o.y = o.y / g_s[vv.y];
    ((float2*)out)[t] = o;
}

extern "C" void kernel_launch(void* const* d_in, const int* in_sizes, int n_in,
                              void* d_out, int out_size) {
    const float* f0    = (const float*)d_in[0];
    const float* f1    = (const float*)d_in[1];
    const float* dist  = (const float*)d_in[2];
    const int*   u     = (const int*)d_in[3];
    const int*   v     = (const int*)d_in[4];
    const float* wq    = (const float*)d_in[5];
    const float* wj00  = (const float*)d_in[6];
    const float* wj01  = (const float*)d_in[7];
    const float* wj10  = (const float*)d_in[8];
    const float* wj11  = (const float*)d_in[9];
    const float* rW1   = (const float*)d_in[10];
    const float* rb1   = (const float*)d_in[11];
    const float* g1    = (const float*)d_in[12];
    const float* be1   = (const float*)d_in[13];
    const float* rW2   = (const float*)d_in[14];
    const float* rb2   = (const float*)d_in[15];
    const float* g2    = (const float*)d_in[16];
    const float* be2   = (const float*)d_in[17];
    const float* W3_00 = (const float*)d_in[18];
    const float* b3_00 = (const float*)d_in[19];
    const float* W3_01 = (const float*)d_in[20];
    const float* b3_01 = (const float*)d_in[21];
    const float* W3_10 = (const float*)d_in[22];
    const float* b3_10 = (const float*)d_in[23];
    const float* W3_11 = (const float*)d_in[24];
    const float* b3_11 = (const float*)d_in[25];
    float* out = (float*)d_out;

    init_kernel<<<(N_NODES + 255) / 256, 256>>>(f0, f1, wq);
    edge_kernel<<<N_EDGES / 128, 128>>>(
        f0, f1, dist, u, v, wj00, wj01, wj10, wj11,
        rW1, rb1, g1, be1, rW2, rb2, g2, be2,
        W3_00, b3_00, W3_01, b3_01, W3_10, b3_10, W3_11, b3_11);
    exp_kernel<<<HALF_E / 256, 256>>>(v, out);
    norm_kernel<<<HALF_E / 256, 256>>>(v, out);
}

// round 17
// speedup vs baseline: 1.0060x; 1.0060x over previous
#include <cuda_runtime.h>
#include <math.h>

#define N_NODES 100000
#define N_EDGES 1600000
#define HALF_E  (N_EDGES / 2)
#define WJPITCH 29

typedef unsigned long long u64;

__device__ float g_dot[N_EDGES];
__device__ float g_m[N_NODES];
__device__ float g_s[N_NODES];
__device__ float g_q[N_NODES * 8];

// ---- packed f32x2 helpers ----
union PU { u64 u; float2 f; };

__device__ __forceinline__ u64 pk(float lo, float hi) {
    PU p; p.f.x = lo; p.f.y = hi; return p.u;
}
__device__ __forceinline__ float2 upk2(u64 x) { PU p; p.u = x; return p.f; }

__device__ __forceinline__ u64 fma2(u64 a, u64 b, u64 c) {
    u64 d; asm("fma.rn.f32x2 %0,%1,%2,%3;" : "=l"(d) : "l"(a), "l"(b), "l"(c)); return d;
}
__device__ __forceinline__ u64 add2(u64 a, u64 b) {
    u64 d; asm("add.rn.f32x2 %0,%1,%2;" : "=l"(d) : "l"(a), "l"(b)); return d;
}
__device__ __forceinline__ u64 mul2(u64 a, u64 b) {
    u64 d; asm("mul.rn.f32x2 %0,%1,%2;" : "=l"(d) : "l"(a), "l"(b)); return d;
}

#define C_NEG1      0xBF800000BF800000ull   // (-1.f, -1.f)
#define C_SIXTEENTH 0x3D8000003D800000ull   // (0.0625f, 0.0625f)

// weights packed across MLP PAIRS: lane lo = MLP 2p, lane hi = MLP 2p+1
// W1/b1/W2/b2 are column-mean-centered at staging time (exact LN mean-folding).
struct SWQ {
    u64 W1[2][3][16];
    u64 b1[2][16], g1[2][16], be1[2][16];
    u64 W2[2][16][16];
    u64 b2[2][16], g2[2][16], be2[2][16];
    u64 W3p0[16][4];    // (W3_00, W3_01)
    u64 b3p0[4];
    u64 W3p1[16][12];   // o<4: (W3_10, W3_11); o>=4: (0, W3_11)
    u64 b3p1[12];
};

// mean-free LN (inputs centered by weight construction): var = sum(h^2)/16 >= 0, NaN-proof
__device__ __forceinline__ void ln_lite_pk(u64* h, const u64* g, const u64* be) {
    u64 q0 = mul2(h[0], h[0]);  q0 = fma2(h[1], h[1], q0);
    u64 q1 = mul2(h[2], h[2]);  q1 = fma2(h[3], h[3], q1);
    u64 q2 = mul2(h[4], h[4]);  q2 = fma2(h[5], h[5], q2);
    u64 q3 = mul2(h[6], h[6]);  q3 = fma2(h[7], h[7], q3);
    u64 q4 = mul2(h[8], h[8]);  q4 = fma2(h[9], h[9], q4);
    u64 q5 = mul2(h[10], h[10]); q5 = fma2(h[11], h[11], q5);
    u64 q6 = mul2(h[12], h[12]); q6 = fma2(h[13], h[13], q6);
    u64 q7 = mul2(h[14], h[14]); q7 = fma2(h[15], h[15], q7);
    q0 = add2(q0, q1); q2 = add2(q2, q3); q4 = add2(q4, q5); q6 = add2(q6, q7);
    q0 = add2(q0, q2); q4 = add2(q4, q6);
    u64 ss = add2(q0, q4);
    float2 V = upk2(ss);
    u64 invb = pk(rsqrtf(fmaf(V.x, 0.0625f, 1e-5f)),
                  rsqrtf(fmaf(V.y, 0.0625f, 1e-5f)));
#pragma unroll
    for (int j = 0; j < 16; j++) {
        PU val; val.u = fma2(mul2(h[j], invb), g[j], be[j]);
        val.f.x = fmaxf(val.f.x, 0.f);
        val.f.y = fmaxf(val.f.y, 0.f);
        h[j] = val.u;
    }
}

template <int OUT>
__device__ __forceinline__ void radial_pair(const SWQ& sw, int p, const u64* W3, const u64* b3,
                                            u64 va, u64 vb, u64 vc, u64* R) {
    u64 h[16];
#pragma unroll
    for (int j = 0; j < 16; j++) h[j] = sw.b1[p][j];
#pragma unroll
    for (int j = 0; j < 16; j++) h[j] = fma2(va, sw.W1[p][0][j], h[j]);
#pragma unroll
    for (int j = 0; j < 16; j++) h[j] = fma2(vb, sw.W1[p][1][j], h[j]);
#pragma unroll
    for (int j = 0; j < 16; j++) h[j] = fma2(vc, sw.W1[p][2][j], h[j]);
    ln_lite_pk(h, sw.g1[p], sw.be1[p]);

    u64 acc[16];
#pragma unroll
    for (int j = 0; j < 16; j++) acc[j] = sw.b2[p][j];
#pragma unroll
    for (int k = 0; k < 16; k++) {
#pragma unroll
        for (int j = 0; j < 16; j++)
            acc[j] = fma2(h[k], sw.W2[p][k][j], acc[j]);
    }
    ln_lite_pk(acc, sw.g2[p], sw.be2[p]);

#pragma unroll
    for (int o = 0; o < OUT; o++) R[o] = b3[o];
#pragma unroll
    for (int k = 0; k < 16; k++) {
#pragma unroll
        for (int o = 0; o < OUT; o++)
            R[o] = fma2(acc[k], W3[k * OUT + o], R[o]);
    }
}

__device__ __forceinline__ void atomicMaxF(float* addr, float val) {
    if (val >= 0.f) atomicMax((int*)addr, __float_as_int(val));
    else            atomicMin((unsigned int*)addr, __float_as_uint(val));
}

// init m/s AND precompute per-node q
__global__ void init_kernel(const float* __restrict__ f0, const float* __restrict__ f1,
                            const float* __restrict__ wq) {
    int n = blockIdx.x * blockDim.x + threadIdx.x;
    if (n >= N_NODES) return;
    g_m[n] = -INFINITY;
    g_s[n] = 0.f;
    float2 f = ((const float2*)f0)[n];
    float f1v[6];
    {
        const float2* p = (const float2*)f1 + 3 * n;
        float2 x;
        x = p[0]; f1v[0] = x.x; f1v[1] = x.y;
        x = p[1]; f1v[2] = x.x; f1v[3] = x.y;
        x = p[2]; f1v[4] = x.x; f1v[5] = x.y;
    }
    float q[8];
#pragma unroll
    for (int o = 0; o < 2; o++) {
        q[o] = fmaf(wq[o * 2 + 0], f.x, wq[o * 2 + 1] * f.y);
#pragma unroll
        for (int m = 0; m < 3; m++)
            q[2 + o * 3 + m] = fmaf(wq[4 + o * 2 + 0], f1v[m], wq[4 + o * 2 + 1] * f1v[3 + m]);
    }
    float4* dst = (float4*)&g_q[n * 8];
    dst[0] = make_float4(q[0], q[1], q[2], q[3]);
    dst[1] = make_float4(q[4], q[5], q[6], q[7]);
}

__global__ __launch_bounds__(128, 4) void edge_kernel(
    const float* __restrict__ f0, const float* __restrict__ f1,
    const float* __restrict__ dist,
    const int* __restrict__ u, const int* __restrict__ v,
    const float* __restrict__ wj00, const float* __restrict__ wj01,
    const float* __restrict__ wj10, const float* __restrict__ wj11,
    const float* __restrict__ rW1, const float* __restrict__ rb1,
    const float* __restrict__ g1, const float* __restrict__ be1,
    const float* __restrict__ rW2, const float* __restrict__ rb2,
    const float* __restrict__ g2, const float* __restrict__ be2,
    const float* __restrict__ W3_00, const float* __restrict__ b3_00,
    const float* __restrict__ W3_01, const float* __restrict__ b3_01,
    const float* __restrict__ W3_10, const float* __restrict__ b3_10,
    const float* __restrict__ W3_11, const float* __restrict__ b3_11)
{
    __shared__ SWQ sw;
    __shared__ float wj11s[128 * WJPITCH];
    __shared__ u64 mrow[42];   // packed row means: W2[0..31], W1[32..37], b1[38..39], b2[40..41]
    {
        int t = threadIdx.x;
        for (int i = t; i < 96; i += 128) {
            int p = i / 48, r = i - p * 48;
            ((u64*)sw.W1)[i] = pk(rW1[(2 * p) * 48 + r], rW1[(2 * p + 1) * 48 + r]);
        }
        for (int i = t; i < 32; i += 128) {
            int p = i / 16, j = i - p * 16;
            ((u64*)sw.b1)[i]  = pk(rb1[(2 * p) * 16 + j], rb1[(2 * p + 1) * 16 + j]);
            ((u64*)sw.g1)[i]  = pk(g1[(2 * p) * 16 + j],  g1[(2 * p + 1) * 16 + j]);
            ((u64*)sw.be1)[i] = pk(be1[(2 * p) * 16 + j], be1[(2 * p + 1) * 16 + j]);
            ((u64*)sw.b2)[i]  = pk(rb2[(2 * p) * 16 + j], rb2[(2 * p + 1) * 16 + j]);
            ((u64*)sw.g2)[i]  = pk(g2[(2 * p) * 16 + j],  g2[(2 * p + 1) * 16 + j]);
            ((u64*)sw.be2)[i] = pk(be2[(2 * p) * 16 + j], be2[(2 * p + 1) * 16 + j]);
        }
        for (int i = t; i < 512; i += 128) {
            int p = i / 256, r = i - p * 256;
            ((u64*)sw.W2)[i] = pk(rW2[(2 * p) * 256 + r], rW2[(2 * p + 1) * 256 + r]);
        }
        for (int i = t; i < 64; i += 128)
            ((u64*)sw.W3p0)[i] = pk(W3_00[i], W3_01[i]);
        for (int i = t; i < 4; i += 128)
            sw.b3p0[i] = pk(b3_00[i], b3_01[i]);
        for (int i = t; i < 192; i += 128) {
            int k = i / 12, o = i - k * 12;
            float lo = (o < 4) ? W3_10[k * 4 + o] : 0.f;
            ((u64*)sw.W3p1)[i] = pk(lo, W3_11[k * 12 + o]);
        }
        for (int i = t; i < 12; i += 128)
            sw.b3p1[i] = pk((i < 4) ? b3_10[i] : 0.f, b3_11[i]);

        const float* src = wj11 + (long long)blockIdx.x * 128 * 27;
#pragma unroll
        for (int k = 0; k < 27; k++) {
            int i = t + 128 * k;
            int e = i / 27, j = i - e * 27;
            wj11s[e * WJPITCH + j] = src[i];
        }
        __syncthreads();

        // ---- packed row means for LN mean-folding ----
        if (t < 42) {
            const u64* row;
            if (t < 32)      row = &((const u64*)sw.W2)[t * 16];
            else if (t < 38) row = &((const u64*)sw.W1)[(t - 32) * 16];
            else if (t < 40) row = &((const u64*)sw.b1)[(t - 38) * 16];
            else             row = &((const u64*)sw.b2)[(t - 40) * 16];
            u64 s = row[0];
#pragma unroll
            for (int j = 1; j < 16; j++) s = add2(s, row[j]);
            mrow[t] = mul2(s, C_SIXTEENTH);
        }
        __syncthreads();
        // ---- subtract means (exact) ----
        for (int i = t; i < 512; i += 128)
            ((u64*)sw.W2)[i] = fma2(mrow[i >> 4], C_NEG1, ((u64*)sw.W2)[i]);
        for (int i = t; i < 96; i += 128)
            ((u64*)sw.W1)[i] = fma2(mrow[32 + (i >> 4)], C_NEG1, ((u64*)sw.W1)[i]);
        for (int i = t; i < 32; i += 128) {
            ((u64*)sw.b1)[i] = fma2(mrow[38 + (i >> 4)], C_NEG1, ((u64*)sw.b1)[i]);
            ((u64*)sw.b2)[i] = fma2(mrow[40 + (i >> 4)], C_NEG1, ((u64*)sw.b2)[i]);
        }
    }
    __syncthreads();

    int e = blockIdx.x * 128 + threadIdx.x;

    // hoisted per-edge loads
    int uu = u[e], vv = v[e];
    float v2 = dist[e];
    float wj00e = wj00[e];
    float wj01v[3], wj10v[3];
#pragma unroll
    for (int m = 0; m < 3; m++) { wj01v[m] = wj01[3 * e + m]; wj10v[m] = wj10[3 * e + m]; }
    float2 fu = ((const float2*)f0)[uu];
    float2 fv = ((const float2*)f0)[vv];
    float f1v[6];
    {
        const float2* p0 = (const float2*)f1 + 3 * vv;
        float2 x;
        x = p0[0]; f1v[0] = x.x; f1v[1] = x.y;
        x = p0[1]; f1v[2] = x.x; f1v[3] = x.y;
        x = p0[2]; f1v[4] = x.x; f1v[5] = x.y;
    }
    float4 qa = ((const float4*)&g_q[vv * 8])[0];
    float4 qb = ((const float4*)&g_q[vv * 8])[1];

    float v0 = fu.x * fv.x;
    float v1 = fu.y * fv.y;
    u64 va = pk(v0, v0), vb = pk(v1, v1), vc = pk(v2, v2);

    float k00, k01;
    float k1[2][3];

    // ==== pair 0: MLP0 (l=0,k=0) lo, MLP1 (l=0,k=1) hi ====
    {
        u64 R[4];
        radial_pair<4>(sw, 0, (const u64*)sw.W3p0, sw.b3p0, va, vb, vc, R);
        float2 r0 = upk2(R[0]), r1 = upk2(R[1]), r2 = upk2(R[2]), r3 = upk2(R[3]);
        k00 = wj00e * fmaf(r0.x, fv.x, r1.x * fv.y);
        k01 = wj00e * fmaf(r2.x, fv.x, r3.x * fv.y);
        float t0 = fmaf(wj01v[0], f1v[0], fmaf(wj01v[1], f1v[1], wj01v[2] * f1v[2]));
        float t1 = fmaf(wj01v[0], f1v[3], fmaf(wj01v[1], f1v[4], wj01v[2] * f1v[5]));
        k00 = fmaf(r0.y, t0, fmaf(r1.y, t1, k00));
        k01 = fmaf(r2.y, t0, fmaf(r3.y, t1, k01));
    }

    // ==== pair 1: MLP2 (l=1,k=0) lo, MLP3 (l=1,k=1) hi ====
    {
        u64 R[12];
        radial_pair<12>(sw, 1, (const u64*)sw.W3p1, sw.b3p1, va, vb, vc, R);
        {
            float2 r0 = upk2(R[0]), r1 = upk2(R[1]), r2 = upk2(R[2]), r3 = upk2(R[3]);
            float d0 = fmaf(r0.x, fv.x, r1.x * fv.y);
            float d1 = fmaf(r2.x, fv.x, r3.x * fv.y);
#pragma unroll
            for (int l = 0; l < 3; l++) {
                k1[0][l] = d0 * wj10v[l];
                k1[1][l] = d1 * wj10v[l];
            }
        }
        const float* wr = &wj11s[threadIdx.x * WJPITCH];
#pragma unroll
        for (int j = 0; j < 3; j++) {
            float r0 = upk2(R[4 * j + 0]).y;
            float r1 = upk2(R[4 * j + 1]).y;
            float r2 = upk2(R[4 * j + 2]).y;
            float r3 = upk2(R[4 * j + 3]).y;
#pragma unroll
            for (int l = 0; l < 3; l++) {
                float w0 = wr[9 * j + 3 * l], w1 = wr[9 * j + 3 * l + 1], w2 = wr[9 * j + 3 * l + 2];
                float s0 = fmaf(w0, f1v[0], fmaf(w1, f1v[1], w2 * f1v[2]));
                float s1 = fmaf(w0, f1v[3], fmaf(w1, f1v[4], w2 * f1v[5]));
                k1[0][l] = fmaf(r0, s0, fmaf(r1, s1, k1[0][l]));
                k1[1][l] = fmaf(r2, s0, fmaf(r3, s1, k1[1][l]));
            }
        }
    }

    // ---- dot with precomputed q ----
    float dot = qa.x * k00;
    dot = fmaf(qa.y, k01, dot);
    dot = fmaf(qa.z, k1[0][0], dot);
    dot = fmaf(qa.w, k1[0][1], dot);
    dot = fmaf(qb.x, k1[0][2], dot);
    dot = fmaf(qb.y, k1[1][0], dot);
    dot = fmaf(qb.z, k1[1][1], dot);
    dot = fmaf(qb.w, k1[1][2], dot);

    g_dot[e] = dot;
    atomicMaxF(&g_m[vv], dot);
}

__global__ void exp_kernel(const int* __restrict__ v, float* __restrict__ out) {
    int t = blockIdx.x * 256 + threadIdx.x;
    if (t >= HALF_E) return;
    int2 vv = ((const int2*)v)[t];
    float2 d = ((const float2*)g_dot)[t];
    float p0 = __expf(d.x - g_m[vv.x]);
    float p1 = __expf(d.y - g_m[vv.y]);
    float2 po; po.x = p0; po.y = p1;
    ((float2*)out)[t] = po;
    atomicAdd(&g_s[vv.x], p0);
    atomicAdd(&g_s[vv.y], p1);
}

__global__ void norm_kernel(const int* __restrict__ v, float* __restrict__ out) {
    int t = blockIdx.x * 256 + threadIdx.x;
    if (t >= HALF_E) return;
    int2 vv = ((const int2*)v)[t];
    float2 o = ((const float2*)out)[t];
    o.x = o.x / g_s[vv.x];
    o.y = o.y / g_s[vv.y];
    ((float2*)out)[t] = o;
}

extern "C" void kernel_launch(void* const* d_in, const int* in_sizes, int n_in,
                              void* d_out, int out_size) {
    const float* f0    = (const float*)d_in[0];
    const float* f1    = (const float*)d_in[1];
    const float* dist  = (const float*)d_in[2];
    const int*   u     = (const int*)d_in[3];
    const int*   v     = (const int*)d_in[4];
    const float* wq    = (const float*)d_in[5];
    const float* wj00  = (const float*)d_in[6];
    const float* wj01  = (const float*)d_in[7];
    const float* wj10  = (const float*)d_in[8];
    const float* wj11  = (const float*)d_in[9];
    const float* rW1   = (const float*)d_in[10];
    const float* rb1   = (const float*)d_in[11];
    const float* g1    = (const float*)d_in[12];
    const float* be1   = (const float*)d_in[13];
    const float* rW2   = (const float*)d_in[14];
    const float* rb2   = (const float*)d_in[15];
    const float* g2    = (const float*)d_in[16];
    const float* be2   = (const float*)d_in[17];
    const float* W3_00 = (const float*)d_in[18];
    const float* b3_00 = (const float*)d_in[19];
    const float* W3_01 = (const float*)d_in[20];
    const float* b3_01 = (const float*)d_in[21];
    const float* W3_10 = (const float*)d_in[22];
    const float* b3_10 = (const float*)d_in[23];
    const float* W3_11 = (const float*)d_in[24];
    const float* b3_11 = (const float*)d_in[25];
    float* out = (float*)d_out;

    init_kernel<<<(N_NODES + 255) / 256, 256>>>(f0, f1, wq);
    edge_kernel<<<N_EDGES / 128, 128>>>(
        f0, f1, dist, u, v, wj00, wj01, wj10, wj11,
        rW1, rb1, g1, be1, rW2, rb2, g2, be2,
        W3_00, b3_00, W3_01, b3_01, W3_10, b3_10, W3_11, b3_11);
    exp_kernel<<<HALF_E / 256, 256>>>(v, out);
    norm_kernel<<<HALF_E / 256, 256>>>(v, out);
}